// round 5
// baseline (speedup 1.0000x reference)
#include <cuda_runtime.h>
#include <cstdint>

// LMNN loss on GB300 — decoupled producer/consumer pipeline.
// outputs: [2048, 512, 128] f32, label_inds: [2048, 511] i32, out: scalar f32.
//
// 256 persistent CTAs (2/SM, single wave), 8 contiguous segments each.
// Warp 0 = producer: streams the CTA's 2 MB via cp.async.bulk into a
// 3-stage x 32KB smem ring (mbarrier full/empty). Warps 1-8 = consumers:
// warp-per-point d2 from smem (LDS.128 + shuffle reduce), then pull/push
// reductions. Last CTA (self-resetting ticket) reduces 256 partials.

#define NSEG   2048
#define PPS    512
#define DDIM   128
#define NPTS   511
#define NCTA   256
#define SPC    8          // segments per CTA
#define NTHR   288        // 9 warps
#define NCONS  256        // consumer threads (warps 1..8)
#define STAGES 3
#define TPTS   64         // points per tile
#define TBYTES 32768      // 64 * 512 B
#define TPS    8          // tiles per segment
#define TTOT   (SPC * TPS)  // 64 tiles per CTA

__device__ float    g_partial[NCTA];
__device__ unsigned g_ticket = 0;   // self-resets via atomicInc wrap

__device__ __forceinline__ uint32_t smem_u32(const void* p) {
    uint32_t a;
    asm("{ .reg .u64 t; cvta.to.shared.u64 t, %1; cvt.u32.u64 %0, t; }"
        : "=r"(a) : "l"(p));
    return a;
}

#define MBAR_INIT(a, c) \
    asm volatile("mbarrier.init.shared.b64 [%0], %1;" :: "r"(a), "r"(c) : "memory")
#define MBAR_EXPECT_TX(a, b) \
    asm volatile("mbarrier.arrive.expect_tx.shared.b64 _, [%0], %1;" :: "r"(a), "r"(b) : "memory")
#define MBAR_ARRIVE(a) \
    asm volatile("mbarrier.arrive.shared.b64 _, [%0];" :: "r"(a) : "memory")

#define MBAR_WAIT_ACQ(mbar, par) do {                                          \
    asm volatile(                                                              \
        "{\n\t.reg .pred P;\n\t"                                               \
        "WL_%=:\n\t"                                                           \
        "mbarrier.try_wait.parity.acquire.cta.shared::cta.b64 P, [%0], %1, 0x989680;\n\t" \
        "@P bra.uni WD_%=;\n\t"                                                \
        "bra.uni WL_%=;\n\t"                                                   \
        "WD_%=:\n\t}"                                                          \
        :: "r"(mbar), "r"(par) : "memory");                                    \
} while (0)

#define MBAR_WAIT_RLX(mbar, par) do {                                          \
    asm volatile(                                                              \
        "{\n\t.reg .pred P;\n\t"                                               \
        "WL_%=:\n\t"                                                           \
        "mbarrier.try_wait.parity.relaxed.cta.shared::cta.b64 P, [%0], %1, 0x989680;\n\t" \
        "@P bra.uni WD_%=;\n\t"                                                \
        "bra.uni WL_%=;\n\t"                                                   \
        "WD_%=:\n\t}"                                                          \
        :: "r"(mbar), "r"(par) : "memory");                                    \
} while (0)

#define BULK_G2S(dst, src, bytes, bar)                                         \
    asm volatile("cp.async.bulk.shared::cta.global.mbarrier::complete_tx::bytes " \
                 "[%0], [%1], %2, [%3];"                                       \
                 :: "r"(dst), "l"(src), "r"(bytes), "r"(bar) : "memory")

#define CBAR() asm volatile("bar.sync 1, 256;" ::: "memory")  // consumers only

__global__ __launch_bounds__(NTHR, 2)
void lmnn_kernel(const float* __restrict__ outputs,
                 const int*   __restrict__ labels,
                 float*       __restrict__ out)
{
    extern __shared__ char dsmem[];                       // STAGES * TBYTES
    __shared__ __align__(8) unsigned long long mbar[2 * STAGES];
    __shared__ float sh_d2[NPTS];
    __shared__ int   sh_same[NPTS];
    __shared__ float sh_red[8];
    __shared__ float sh_fred[9];
    __shared__ int   sh_last;

    const int tid = threadIdx.x;
    const int cta = blockIdx.x;

    const uint32_t full_b  = smem_u32(&mbar[0]);
    const uint32_t empty_b = smem_u32(&mbar[STAGES]);
    const uint32_t buf_b   = smem_u32(dsmem);

    if (tid == 0) {
        #pragma unroll
        for (int s = 0; s < STAGES; s++) {
            MBAR_INIT(full_b  + 8u * s, 1);   // producer's expect_tx arrival
            MBAR_INIT(empty_b + 8u * s, 8);   // one arrive per consumer warp
        }
    }
    __syncthreads();

    if (tid < 32) {
        // ---- producer warp (thread 0 does all issue work) ----
        if (tid == 0) {
            int st = 0, ph = 1;  // fresh barrier: first empty-wait passes
            const char* src0 = (const char*)outputs
                             + (size_t)cta * SPC * PPS * DDIM * sizeof(float);
            for (int gt = 0; gt < TTOT; ++gt) {
                MBAR_WAIT_RLX(empty_b + 8u * st, ph);
                MBAR_EXPECT_TX(full_b + 8u * st, TBYTES);
                BULK_G2S(buf_b + (uint32_t)st * TBYTES,
                         src0 + (size_t)gt * TBYTES,
                         (uint32_t)TBYTES,
                         full_b + 8u * st);
                if (++st == STAGES) { st = 0; ph ^= 1; }
            }
        }
    } else {
        // ---- consumer warps: ctid in [0,256), cw in [0,8) ----
        const int ctid = tid - 32;
        const int cw   = ctid >> 5;
        const int lane = ctid & 31;
        int st = 0, ph = 0;
        float acc = 0.0f;

        for (int s = 0; s < SPC; ++s) {
            const int seg = cta * SPC + s;
            CBAR();  // previous segment's sh_d2/sh_same reads are done

            const int* lab  = labels + (size_t)seg * NPTS;
            const int  lab0 = __ldg(lab);
            for (int j = ctid; j < NPTS; j += NCONS)
                sh_same[j] = (__ldg(lab + j) == lab0);

            float4 c = make_float4(0.f, 0.f, 0.f, 0.f);
            for (int t = 0; t < TPS; ++t) {
                MBAR_WAIT_ACQ(full_b + 8u * st, ph);
                const float4* tb = (const float4*)(dsmem + st * TBYTES);
                if (t == 0) c = tb[lane];  // center row = point 0 of tile 0

                const int lp0 = cw * 8;    // this warp's 8 points in the tile
                #pragma unroll
                for (int k = 0; k < 8; k++) {
                    const float4 p = tb[(lp0 + k) * 32 + lane];
                    const float dx = p.x - c.x;
                    const float dy = p.y - c.y;
                    const float dz = p.z - c.z;
                    const float dw = p.w - c.w;
                    float v = dx * dx + dy * dy + dz * dz + dw * dw;
                    #pragma unroll
                    for (int o = 16; o > 0; o >>= 1)
                        v += __shfl_xor_sync(0xffffffffu, v, o);
                    const int gp = t * TPTS + lp0 + k;
                    if (lane == 0 && gp > 0) sh_d2[gp - 1] = v;
                }
                if (lane == 0) MBAR_ARRIVE(empty_b + 8u * st);
                if (++st == STAGES) { st = 0; ph ^= 1; }
            }
            CBAR();  // sh_d2 / sh_same complete

            // pull = min d2 over same-label (j=0 always same-label)
            float lmin = __int_as_float(0x7f800000);
            for (int j = ctid; j < NPTS; j += NCONS)
                if (sh_same[j]) lmin = fminf(lmin, sh_d2[j]);
            #pragma unroll
            for (int o = 16; o > 0; o >>= 1)
                lmin = fminf(lmin, __shfl_xor_sync(0xffffffffu, lmin, o));
            if (lane == 0) sh_red[cw] = lmin;
            CBAR();

            float pull = sh_red[0];
            #pragma unroll
            for (int w = 1; w < 8; w++) pull = fminf(pull, sh_red[w]);
            const float margin = 1.0f + pull;

            float lsum = 0.0f;
            for (int j = ctid; j < NPTS; j += NCONS)
                if (!sh_same[j]) lsum += fmaxf(margin - sh_d2[j], 0.0f);
            #pragma unroll
            for (int o = 16; o > 0; o >>= 1)
                lsum += __shfl_xor_sync(0xffffffffu, lsum, o);
            CBAR();  // all pull reads of sh_red done before overwrite
            if (lane == 0) sh_red[cw] = lsum;
            CBAR();

            if (ctid == 0) {
                float push = 0.0f;
                #pragma unroll
                for (int w = 0; w < 8; w++) push += sh_red[w];
                acc += pull + push;
            }
        }

        if (ctid == 0) {
            g_partial[cta] = acc;
            __threadfence();
            // wraps to 0 when old == NCTA-1 -> deterministic across replays
            const unsigned old = atomicInc(&g_ticket, NCTA - 1);
            sh_last = (old == NCTA - 1);
        }
    }
    __syncthreads();

    if (sh_last) {
        float a2 = 0.0f;
        const volatile float* vp = g_partial;
        if (tid < NCTA) a2 = vp[tid];
        #pragma unroll
        for (int o = 16; o > 0; o >>= 1)
            a2 += __shfl_xor_sync(0xffffffffu, a2, o);
        if ((tid & 31) == 0) sh_fred[tid >> 5] = a2;
        __syncthreads();
        if (tid == 0) {
            float tot = 0.0f;
            #pragma unroll
            for (int w = 0; w < 9; w++) tot += sh_fred[w];
            *out = tot / (float)((size_t)NSEG * PPS);
        }
    }
}

extern "C" void kernel_launch(void* const* d_in, const int* in_sizes, int n_in,
                              void* d_out, int out_size)
{
    const float* outputs = (const float*)d_in[0];
    const int*   labels  = (const int*)d_in[1];
    float*       out     = (float*)d_out;

    cudaFuncSetAttribute(lmnn_kernel,
                         cudaFuncAttributeMaxDynamicSharedMemorySize,
                         STAGES * TBYTES);
    lmnn_kernel<<<NCTA, NTHR, STAGES * TBYTES>>>(outputs, labels, out);
}